// round 7
// baseline (speedup 1.0000x reference)
#include <cuda_runtime.h>

#define T_DIM   2000
#define KFR     400
#define KD      400
#define A_DIM   100
#define NB      (KFR / 16)             // 25 batches of 16 rows per slab
#define SLABS   2                      // t-slabs per block
#define GRID    (T_DIM / SLABS)        // 1000 blocks
#define NBTOT   (NB * SLABS)           // 50 batches over 2 contiguous slabs
#define EPSF    1e-24f

typedef unsigned long long u64;

// f32x2 packed-FMA helpers (FFMA2 — PTX-only, ptxas won't auto-fuse)
__device__ __forceinline__ u64 pack2(float lo, float hi) {
    u64 r; asm("mov.b64 %0, {%1, %2};" : "=l"(r) : "f"(lo), "f"(hi)); return r;
}
__device__ __forceinline__ void unpack2(u64 v, float& lo, float& hi) {
    asm("mov.b64 {%0, %1}, %2;" : "=f"(lo), "=f"(hi) : "l"(v));
}
__device__ __forceinline__ u64 ffma2(u64 a, u64 b, u64 c) {
    u64 d; asm("fma.rn.f32x2 %0, %1, %2, %3;" : "=l"(d) : "l"(a), "l"(b), "l"(c));
    return d;
}

// Accumulators: [0..99]=Ga, [100..199]=Ha, [200]=P1, [201]=P2.
// Self-cleaning: the last block zeroes after the fused finalize.
__device__ float d_acc[2 * A_DIM + 2];
__device__ unsigned int d_done;

// One block per pair of adjacent time slabs (contiguous 320KB of X).
// Packed butterfly: 9 shfl reduce 4 row-dots into disjoint 8-lane groups so
// exp/log/div run once per group. X rows loaded as ulonglong2 so FFMA2
// (f32x2) does dots and the Ga/Ha accumulation at half the FMA issue count.
// phi_fr folded at row level; last block runs the scalar finalize inline.
__global__ __launch_bounds__(128) void mmdglm_main(
    const float* __restrict__ tg, const int* __restrict__ mask,
    const float* __restrict__ X, const float* __restrict__ theta,
    const float* __restrict__ phi_fr, const float* __restrict__ phi_d,
    float* __restrict__ out)
{
    const int warp  = threadIdx.x >> 5;
    const int lane  = threadIdx.x & 31;
    const int tid   = threadIdx.x;
    const float dt  = tg[1] - tg[0];
    const unsigned FULL = 0xffffffffu;
    const u64 Z64 = 0ull;

    // theta packed as f32x2 pairs (loop-invariant)
    u64 th01 = Z64, th23 = Z64;
    if (lane < 25) {
        float4 th = __ldg(((const float4*)theta) + lane);
        th01 = pack2(th.x, th.y);
        th23 = pack2(th.z, th.w);
    }

    // packed-butterfly group -> row: lanes 0-7 r0, 8-15 r2, 16-23 r1, 24-31 r3
    const int myrow = (((lane >> 3) & 1) << 1) | ((lane >> 4) & 1);

    u64 Ga01 = Z64, Ga23 = Z64, Ha01 = Z64, Ha23 = Z64;
    float p1acc = 0.f, p2acc = 0.f;

    const float* slab = X    + (size_t)(blockIdx.x * SLABS) * KFR * A_DIM;
    const int*   mrow = mask + (size_t)(blockIdx.x * SLABS) * KFR;

    // prefetch batch 0
    ulonglong2 z2; z2.x = 0ull; z2.y = 0ull;
    ulonglong2 c0 = z2, c1 = z2, c2 = z2, c3 = z2;
    {
        const float* rowp = slab + (warp * 4) * A_DIM;
        if (lane < 25) {
            c0 = __ldg((const ulonglong2*)(rowp)             + lane);
            c1 = __ldg((const ulonglong2*)(rowp + A_DIM)     + lane);
            c2 = __ldg((const ulonglong2*)(rowp + 2 * A_DIM) + lane);
            c3 = __ldg((const ulonglong2*)(rowp + 3 * A_DIM) + lane);
        }
    }
    int mcur = __ldg(mrow + warp * 4 + myrow);

    #pragma unroll 1
    for (int g = 0; g < NBTOT; g++) {
        const int grbase = g * 16 + warp * 4;          // global row 0..799

        ulonglong2 n0 = z2, n1 = z2, n2 = z2, n3 = z2;
        int mnext = 0;
        if (g + 1 < NBTOT) {
            const int grn = grbase + 16;
            const float* rowp = slab + (size_t)grn * A_DIM;
            if (lane < 25) {
                n0 = __ldg((const ulonglong2*)(rowp)             + lane);
                n1 = __ldg((const ulonglong2*)(rowp + A_DIM)     + lane);
                n2 = __ldg((const ulonglong2*)(rowp + 2 * A_DIM) + lane);
                n3 = __ldg((const ulonglong2*)(rowp + 3 * A_DIM) + lane);
            }
            mnext = __ldg(mrow + grn + myrow);
        }

        const int kbase = (grbase >= KFR) ? (grbase - KFR) : grbase;
        const float pf0 = __ldg(phi_fr + kbase);
        const float pf1 = __ldg(phi_fr + kbase + 1);
        const float pf2 = __ldg(phi_fr + kbase + 2);
        const float pf3 = __ldg(phi_fr + kbase + 3);

        // dots via f32x2 (2 FFMA2 + horizontal add per row)
        float p0, p1, p2, p3;
        {
            float lo, hi;
            unpack2(ffma2(c0.x, th01, ffma2(c0.y, th23, Z64)), lo, hi); p0 = lo + hi;
            unpack2(ffma2(c1.x, th01, ffma2(c1.y, th23, Z64)), lo, hi); p1 = lo + hi;
            unpack2(ffma2(c2.x, th01, ffma2(c2.y, th23, Z64)), lo, hi); p2 = lo + hi;
            unpack2(ffma2(c3.x, th01, ffma2(c3.y, th23, Z64)), lo, hi); p3 = lo + hi;
        }

        // Packed butterfly: 9 shfl reduce all 4 rows.
        float u0 = __shfl_xor_sync(FULL, p0, 16);
        float u1 = __shfl_xor_sync(FULL, p1, 16);
        float w01 = (lane & 16) ? (p1 + u1) : (p0 + u0);
        float u2 = __shfl_xor_sync(FULL, p2, 16);
        float u3 = __shfl_xor_sync(FULL, p3, 16);
        float w23 = (lane & 16) ? (p3 + u3) : (p2 + u2);
        float v01 = __shfl_xor_sync(FULL, w01, 8);
        float v23 = __shfl_xor_sync(FULL, w23, 8);
        float v = (lane & 8) ? (w23 + v23) : (w01 + v01);
        v += __shfl_xor_sync(FULL, v, 4);
        v += __shfl_xor_sync(FULL, v, 2);
        v += __shfl_xor_sync(FULL, v, 1);
        // v = dot of row (grbase + myrow)

        const float r   = __expf(v);            // non_linearity = exp
        const float dtr = dt * r;
        float w, llc;
        if (mcur) {
            // 1 - e^-dtr = (E-1)/E  =>  llc = log(E-1) - dtr  (one exp only)
            const float Em1 = __expf(dtr) - 1.0f;
            w   = __fdividef(dtr, Em1 - EPSF);
            llc = __logf(Em1 + EPSF) - dtr;
        } else {
            w   = -dtr;
            llc = -dtr;
        }
        const float pfmy = (myrow == 0) ? pf0 : (myrow == 1) ? pf1
                         : (myrow == 2) ? pf2 : pf3;
        p1acc += pfmy * llc;                    // 8x redundant; /8 at epilogue
        p2acc += pfmy * pfmy * llc;

        const float w0 = __shfl_sync(FULL, w, 0);
        const float w1 = __shfl_sync(FULL, w, 16);
        const float w2 = __shfl_sync(FULL, w, 8);
        const float w3 = __shfl_sync(FULL, w, 24);

        const float a0 = pf0 * w0, a1 = pf1 * w1, a2 = pf2 * w2, a3 = pf3 * w3;
        const u64 A0 = pack2(a0, a0), A1 = pack2(a1, a1);
        const u64 A2 = pack2(a2, a2), A3 = pack2(a3, a3);
        const u64 H0 = pack2(pf0 * a0, pf0 * a0), H1 = pack2(pf1 * a1, pf1 * a1);
        const u64 H2 = pack2(pf2 * a2, pf2 * a2), H3 = pack2(pf3 * a3, pf3 * a3);

        Ga01 = ffma2(A0, c0.x, Ga01); Ga23 = ffma2(A0, c0.y, Ga23);
        Ga01 = ffma2(A1, c1.x, Ga01); Ga23 = ffma2(A1, c1.y, Ga23);
        Ga01 = ffma2(A2, c2.x, Ga01); Ga23 = ffma2(A2, c2.y, Ga23);
        Ga01 = ffma2(A3, c3.x, Ga01); Ga23 = ffma2(A3, c3.y, Ga23);
        Ha01 = ffma2(H0, c0.x, Ha01); Ha23 = ffma2(H0, c0.y, Ha23);
        Ha01 = ffma2(H1, c1.x, Ha01); Ha23 = ffma2(H1, c1.y, Ha23);
        Ha01 = ffma2(H2, c2.x, Ha01); Ha23 = ffma2(H2, c2.y, Ha23);
        Ha01 = ffma2(H3, c3.x, Ha01); Ha23 = ffma2(H3, c3.y, Ha23);

        c0 = n0; c1 = n1; c2 = n2; c3 = n3; mcur = mnext;
    }

    #pragma unroll
    for (int o = 16; o; o >>= 1) {
        p1acc += __shfl_xor_sync(FULL, p1acc, o);
        p2acc += __shfl_xor_sync(FULL, p2acc, o);
    }
    p1acc *= 0.125f; p2acc *= 0.125f;

    __shared__ float sga[4][A_DIM];
    __shared__ float sha[4][A_DIM];
    __shared__ float sp[4][2];
    if (lane < 25) {
        float g0, g1, g2, g3, h0, h1, h2, h3;
        unpack2(Ga01, g0, g1); unpack2(Ga23, g2, g3);
        unpack2(Ha01, h0, h1); unpack2(Ha23, h2, h3);
        *(float4*)&sga[warp][lane * 4] = make_float4(g0, g1, g2, g3);
        *(float4*)&sha[warp][lane * 4] = make_float4(h0, h1, h2, h3);
    }
    if (lane == 0) { sp[warp][0] = p1acc; sp[warp][1] = p2acc; }
    __syncthreads();

    if (tid < A_DIM) {
        const float ga = sga[0][tid] + sga[1][tid] + sga[2][tid] + sga[3][tid];
        const float ha = sha[0][tid] + sha[1][tid] + sha[2][tid] + sha[3][tid];
        atomicAdd(&d_acc[tid],         ga);
        atomicAdd(&d_acc[A_DIM + tid], ha);
    }
    if (tid == 0)
        atomicAdd(&d_acc[2 * A_DIM],     sp[0][0] + sp[1][0] + sp[2][0] + sp[3][0]);
    if (tid == 1)
        atomicAdd(&d_acc[2 * A_DIM + 1], sp[0][1] + sp[1][1] + sp[2][1] + sp[3][1]);

    // ---- last-block-done fused finalize ----
    __threadfence();
    __shared__ bool amlast;
    if (tid == 0) amlast = (atomicAdd(&d_done, 1u) == (unsigned)(gridDim.x - 1));
    __syncthreads();
    if (!amlast) return;

    volatile float* vacc = d_acc;
    float Ga = 0.f, Ha = 0.f;
    if (tid < A_DIM) { Ga = vacc[tid]; Ha = vacc[A_DIM + tid]; }
    const float P1 = vacc[2 * A_DIM], P2 = vacc[2 * A_DIM + 1];

    float b0 = 0.f, b1 = 0.f, b2 = 0.f, b3 = 0.f;
    for (int i = tid; i < KFR; i += 128) {
        const float pfv = phi_fr[i], pdv = phi_d[i];
        b0 += pfv; b1 += pfv * pfv; b2 += pdv; b3 += pdv * pdv;
    }
    #pragma unroll
    for (int o = 16; o; o >>= 1) {
        b0 += __shfl_xor_sync(FULL, b0, o);
        b1 += __shfl_xor_sync(FULL, b1, o);
        b2 += __shfl_xor_sync(FULL, b2, o);
        b3 += __shfl_xor_sync(FULL, b3, o);
    }
    __shared__ float shp[4][4];
    __shared__ float sc[4];
    if (lane == 0) { shp[warp][0] = b0; shp[warp][1] = b1;
                     shp[warp][2] = b2; shp[warp][3] = b3; }
    __syncthreads();

    // clean state for the next graph replay
    if (tid < A_DIM) { d_acc[tid] = 0.f; d_acc[A_DIM + tid] = 0.f; }
    if (tid == A_DIM) { d_acc[2 * A_DIM] = 0.f; d_acc[2 * A_DIM + 1] = 0.f;
                        d_done = 0u; }

    if (tid < 4) sc[tid] = shp[0][tid] + shp[1][tid] + shp[2][tid] + shp[3][tid];
    __syncthreads();

    const float S_fr = sc[0], Q_fr = sc[1], S_d = sc[2], Q_d = sc[3];
    const float n_fr = 0.5f * (float)KFR * (float)(KFR - 1);
    const float n_d  = 0.5f * (float)KD  * (float)(KD - 1);
    const float inv_kdkfr = 1.0f / ((float)KD * (float)KFR);

    if (tid == 0) {
        out[0] = (P1 * S_fr - P2) / n_fr - 2.0f * S_d * P1 * inv_kdkfr;
        out[1 + A_DIM] = (S_d * S_d - Q_d) / (2.0f * n_d)
                       + (S_fr * S_fr - Q_fr) / (2.0f * n_fr)
                       - 2.0f * S_d * S_fr * inv_kdkfr;
    }
    if (tid < A_DIM) {
        out[1 + tid] = (S_fr * Ga - Ha) / n_fr - 2.0f * S_d * Ga * inv_kdkfr;
    }
}

extern "C" void kernel_launch(void* const* d_in, const int* in_sizes, int n_in,
                              void* d_out, int out_size) {
    const float* t      = (const float*)d_in[0];
    const int*   mask   = (const int*)  d_in[1];
    const float* X      = (const float*)d_in[2];
    const float* theta  = (const float*)d_in[3];
    const float* phi_d  = (const float*)d_in[4];
    const float* phi_fr = (const float*)d_in[5];
    float* out = (float*)d_out;

    mmdglm_main<<<GRID, 128>>>(t, mask, X, theta, phi_fr, phi_d, out);
}